// round 15
// baseline (speedup 1.0000x reference)
#include <cuda_runtime.h>
#include <cuda_bf16.h>
#include <math.h>
#include <stdint.h>

// Problem constants: B=2, S=2048, D=2048, L=256, H=16, hd=128
#define BB   2
#define SS   2048
#define DD   2048
#define LL   256
#define HH   16
#define HD   128
#define MROWS (BB * SS)

// ---------------------------------------------------------------------------
// Scratch
// ---------------------------------------------------------------------------
__device__ float g_q[(size_t)MROWS * DD];
__device__ float g_k[(size_t)MROWS * DD];
__device__ float g_v[(size_t)MROWS * DD];
__device__ float g_ctx[(size_t)MROWS * DD];
__device__ float g_latent[(size_t)MROWS * LL];

__device__ __nv_bfloat16 g_x_hi[(size_t)MROWS * DD];
__device__ __nv_bfloat16 g_x_lo[(size_t)MROWS * DD];
__device__ __nv_bfloat16 g_wq_hi[(size_t)DD * DD];
__device__ __nv_bfloat16 g_wq_lo[(size_t)DD * DD];
__device__ __nv_bfloat16 g_wdkv_hi[(size_t)LL * DD];
__device__ __nv_bfloat16 g_wdkv_lo[(size_t)LL * DD];
__device__ __nv_bfloat16 g_wuk_hi[(size_t)DD * LL];
__device__ __nv_bfloat16 g_wuk_lo[(size_t)DD * LL];
__device__ __nv_bfloat16 g_wuv_hi[(size_t)DD * LL];
__device__ __nv_bfloat16 g_wuv_lo[(size_t)DD * LL];
__device__ __nv_bfloat16 g_wo_hi[(size_t)DD * DD];
__device__ __nv_bfloat16 g_wo_lo[(size_t)DD * DD];
__device__ __nv_bfloat16 g_lat_hi[(size_t)MROWS * LL];
__device__ __nv_bfloat16 g_lat_lo[(size_t)MROWS * LL];
__device__ __nv_bfloat16 g_ctx_hi[(size_t)MROWS * DD];
__device__ __nv_bfloat16 g_ctx_lo[(size_t)MROWS * DD];

// ---------------------------------------------------------------------------
// Split fp32 -> bf16 hi + lo planes.
// ---------------------------------------------------------------------------
__global__ __launch_bounds__(256) void split_kernel(
    const float* __restrict__ src, __nv_bfloat16* __restrict__ hi,
    __nv_bfloat16* __restrict__ lo, int n4)
{
    int i = blockIdx.x * blockDim.x + threadIdx.x;
    if (i >= n4) return;
    float4 v = ((const float4*)src)[i];
    float vv[4];
    vv[0] = v.x; vv[1] = v.y; vv[2] = v.z; vv[3] = v.w;
    __nv_bfloat16 h[4];
    __nv_bfloat16 l[4];
#pragma unroll
    for (int c = 0; c < 4; c++) {
        h[c] = __float2bfloat16(vv[c]);
        l[c] = __float2bfloat16(vv[c] - __bfloat162float(h[c]));
    }
    *(uint2*)(hi + (size_t)i * 4) = *(uint2*)h;
    *(uint2*)(lo + (size_t)i * 4) = *(uint2*)l;
}

// ---------------------------------------------------------------------------
// HMMA / async helpers
// ---------------------------------------------------------------------------
__device__ __forceinline__ uint32_t su32(const void* p) {
    return (uint32_t)__cvta_generic_to_shared(p);
}
__device__ __forceinline__ void ldsm4(uint32_t* r, uint32_t a) {
    asm volatile("ldmatrix.sync.aligned.m8n8.x4.shared.b16 {%0,%1,%2,%3},[%4];"
                 : "=r"(r[0]), "=r"(r[1]), "=r"(r[2]), "=r"(r[3]) : "r"(a));
}
__device__ __forceinline__ void ldsm4t(uint32_t* r, uint32_t a) {
    asm volatile("ldmatrix.sync.aligned.m8n8.x4.trans.shared.b16 {%0,%1,%2,%3},[%4];"
                 : "=r"(r[0]), "=r"(r[1]), "=r"(r[2]), "=r"(r[3]) : "r"(a));
}
__device__ __forceinline__ void mma16816(float* d, const uint32_t* a,
                                         const uint32_t* b) {
    asm volatile(
        "mma.sync.aligned.m16n8k16.row.col.f32.bf16.bf16.f32 "
        "{%0,%1,%2,%3},{%4,%5,%6,%7},{%8,%9},{%0,%1,%2,%3};"
        : "+f"(d[0]), "+f"(d[1]), "+f"(d[2]), "+f"(d[3])
        : "r"(a[0]), "r"(a[1]), "r"(a[2]), "r"(a[3]), "r"(b[0]), "r"(b[1]));
}
__device__ __forceinline__ void cpa16(uint32_t saddr, const void* g) {
    asm volatile("cp.async.ca.shared.global [%0],[%1],16;"
                 :: "r"(saddr), "l"(g));
}
__device__ __forceinline__ void cp_commit() {
    asm volatile("cp.async.commit_group;");
}
template <int N>
__device__ __forceinline__ void cp_wait() {
    asm volatile("cp.async.wait_group %0;" :: "n"(N));
}
__device__ __forceinline__ void split4(const float4 v, uint32_t* hi2,
                                       uint32_t* lo2) {
    float f[4];
    f[0] = v.x; f[1] = v.y; f[2] = v.z; f[3] = v.w;
    __nv_bfloat16 h[4];
    __nv_bfloat16 l[4];
#pragma unroll
    for (int c = 0; c < 4; c++) {
        h[c] = __float2bfloat16(f[c]);
        l[c] = __float2bfloat16(f[c] - __bfloat162float(h[c]));
    }
    hi2[0] = *(uint32_t*)&h[0];
    hi2[1] = *(uint32_t*)&h[2];
    lo2[0] = *(uint32_t*)&l[0];
    lo2[1] = *(uint32_t*)&l[2];
}

// ---------------------------------------------------------------------------
// Split-bf16 GEMM: CTA tile 128x256, K-chunk 64, 512 threads / 16 warps (2x8),
// warp tile 64x32. 12 ldsm -> 48 mma per kc. Terms hh + hl + lh.
// C[M,N] = A[M,K] @ B[N,K]^T (+bias), fp32 acc. N % 256 == 0.
// ---------------------------------------------------------------------------
#define GP 72                         // smem pitch (bf16), 144B rows
#define APLANE (128 * GP)             // 9216 elems
#define BPLANE (256 * GP)             // 18432 elems
#define STG_ELEMS (2 * APLANE + 2 * BPLANE)   // 55296
#define GEMM_SMEM_BYTES (2 * STG_ELEMS * 2)   // 221184 B

__global__ __launch_bounds__(512) void hgemm_split_nt(
    const __nv_bfloat16* __restrict__ Ahi, const __nv_bfloat16* __restrict__ Alo,
    const __nv_bfloat16* __restrict__ Bhi, const __nv_bfloat16* __restrict__ Blo,
    const float* __restrict__ bias, float* __restrict__ C,
    int M, int N, int K)
{
    extern __shared__ __nv_bfloat16 smg[];

    const int t    = threadIdx.x;
    const int lane = t & 31;
    const int warp = t >> 5;
    const int wm   = warp >> 3;       // 0..1
    const int wn   = warp & 7;        // 0..7
    const int row0 = blockIdx.y * 128;
    const int col0 = blockIdx.x * 256;

    // A loader: 4 threads/row, 16 bf16 each. B loader: 2 threads/row, 32 bf16.
    const int lrA = t >> 2;
    const int lkA = (t & 3) * 16;
    const int lrB = t >> 1;
    const int lkB = (t & 1) * 32;
    const __nv_bfloat16* pAh = Ahi + (size_t)(row0 + lrA) * K + lkA;
    const __nv_bfloat16* pAl = Alo + (size_t)(row0 + lrA) * K + lkA;
    const __nv_bfloat16* pBh = Bhi + (size_t)(col0 + lrB) * K + lkB;
    const __nv_bfloat16* pBl = Blo + (size_t)(col0 + lrB) * K + lkB;

    const uint32_t sbA = su32(smg) + (uint32_t)(lrA * GP + lkA) * 2;
    const uint32_t sbB = su32(smg) + (uint32_t)(lrB * GP + lkB) * 2;
    const int nkt = K / 64;

    float acc[4][4][4];
#pragma unroll
    for (int i = 0; i < 4; i++)
#pragma unroll
        for (int j = 0; j < 4; j++)
#pragma unroll
            for (int c = 0; c < 4; c++) acc[i][j][c] = 0.f;

#define FILL_STAGE(stg, ktv)                                                  \
    do {                                                                      \
        if ((ktv) < nkt) {                                                    \
            int adv = (ktv) * 64;                                             \
            uint32_t stb = (uint32_t)((stg) * STG_ELEMS) * 2;                 \
            cpa16(sbA + stb,                       pAh + adv);                \
            cpa16(sbA + stb + 16,                  pAh + adv + 8);            \
            cpa16(sbA + stb + APLANE * 2,          pAl + adv);                \
            cpa16(sbA + stb + APLANE * 2 + 16,     pAl + adv + 8);            \
            uint32_t bb = stb + APLANE * 4;                                   \
            cpa16(sbB + bb,                        pBh + adv);                \
            cpa16(sbB + bb + 16,                   pBh + adv + 8);            \
            cpa16(sbB + bb + 32,                   pBh + adv + 16);           \
            cpa16(sbB + bb + 48,                   pBh + adv + 24);           \
            uint32_t cb = bb + BPLANE * 2;                                    \
            cpa16(sbB + cb,                        pBl + adv);                \
            cpa16(sbB + cb + 16,                   pBl + adv + 8);            \
            cpa16(sbB + cb + 32,                   pBl + adv + 16);           \
            cpa16(sbB + cb + 48,                   pBl + adv + 24);           \
        }                                                                     \
        cp_commit();                                                          \
    } while (0)

    FILL_STAGE(0, 0);

    const int lm_r = (lane & 7) + ((lane >> 3) & 1) * 8;
    const int lm_c = (lane >> 4) * 8;

    for (int kt = 0; kt < nkt; kt++) {
        const int cur = kt & 1;
        cp_wait<0>();
        __syncthreads();

        FILL_STAGE(cur ^ 1, kt + 1);

        const __nv_bfloat16* sAh = smg + cur * STG_ELEMS;
        const __nv_bfloat16* sAl = sAh + APLANE;
        const __nv_bfloat16* sBh = sAh + 2 * APLANE;
        const __nv_bfloat16* sBl = sBh + BPLANE;

#pragma unroll
        for (int kc = 0; kc < 4; kc++) {
            const int c0 = kc * 16 + lm_c;
            uint32_t afr[4][4];
            uint32_t bhf[4][2];
            uint32_t blf[4][2];

#pragma unroll
            for (int mt = 0; mt < 4; mt++) {
                int r = wm * 64 + mt * 16 + lm_r;
                ldsm4(afr[mt], su32(sAh + r * GP + c0));
            }
#pragma unroll
            for (int np = 0; np < 2; np++) {
                int r = wn * 32 + np * 16 + lm_r;
                uint32_t tmp[4];
                ldsm4(tmp, su32(sBh + r * GP + c0));
                bhf[2 * np][0]     = tmp[0]; bhf[2 * np][1]     = tmp[2];
                bhf[2 * np + 1][0] = tmp[1]; bhf[2 * np + 1][1] = tmp[3];
                ldsm4(tmp, su32(sBl + r * GP + c0));
                blf[2 * np][0]     = tmp[0]; blf[2 * np][1]     = tmp[2];
                blf[2 * np + 1][0] = tmp[1]; blf[2 * np + 1][1] = tmp[3];
            }

            // hh
#pragma unroll
            for (int mt = 0; mt < 4; mt++)
#pragma unroll
                for (int nt = 0; nt < 4; nt++)
                    mma16816(acc[mt][nt], afr[mt], bhf[nt]);
            // hl
#pragma unroll
            for (int mt = 0; mt < 4; mt++)
#pragma unroll
                for (int nt = 0; nt < 4; nt++)
                    mma16816(acc[mt][nt], afr[mt], blf[nt]);
            // reload A-lo over afr, then lh
#pragma unroll
            for (int mt = 0; mt < 4; mt++) {
                int r = wm * 64 + mt * 16 + lm_r;
                ldsm4(afr[mt], su32(sAl + r * GP + c0));
            }
#pragma unroll
            for (int mt = 0; mt < 4; mt++)
#pragma unroll
                for (int nt = 0; nt < 4; nt++)
                    mma16816(acc[mt][nt], afr[mt], bhf[nt]);
        }
    }

#pragma unroll
    for (int mt = 0; mt < 4; mt++) {
#pragma unroll
        for (int nt = 0; nt < 4; nt++) {
            int gr = row0 + wm * 64 + mt * 16 + (lane >> 2);
            int gc = col0 + wn * 32 + nt * 8 + (lane & 3) * 2;
            float b0 = 0.f;
            float b1 = 0.f;
            if (bias) { b0 = bias[gc]; b1 = bias[gc + 1]; }
            float2 o0;
            float2 o1;
            o0.x = acc[mt][nt][0] + b0; o0.y = acc[mt][nt][1] + b1;
            o1.x = acc[mt][nt][2] + b0; o1.y = acc[mt][nt][3] + b1;
            *(float2*)(C + (size_t)gr * N + gc)       = o0;
            *(float2*)(C + (size_t)(gr + 8) * N + gc) = o1;
        }
    }
#undef FILL_STAGE
}

// ---------------------------------------------------------------------------
// RoPE in-place on q and k.
// ---------------------------------------------------------------------------
__global__ __launch_bounds__(256) void rope_kernel(float* __restrict__ q,
                                                   float* __restrict__ k)
{
    int idx = blockIdx.x * blockDim.x + threadIdx.x;
    const int total = MROWS * HH * 64;
    if (idx >= total) return;

    int j   = idx & 63;
    int h   = (idx >> 6) & (HH - 1);
    int row = idx >> 10;
    int s   = row & (SS - 1);

    const float LOG2_BASE = 13.287712379549449f;
    float inv = exp2f(-(float)j * (LOG2_BASE / 64.0f));
    float ang = (float)s * inv;
    float c, sn;
    sincosf(ang, &sn, &c);

    size_t base = (size_t)row * DD + h * HD;

    float q1 = q[base + j];
    float q2 = q[base + j + 64];
    q[base + j]      = q1 * c - q2 * sn;
    q[base + j + 64] = q2 * c + q1 * sn;

    float k1 = k[base + j];
    float k2 = k[base + j + 64];
    k[base + j]      = k1 * c - k2 * sn;
    k[base + j + 64] = k2 * c + k1 * sn;
}

// ---------------------------------------------------------------------------
// HMMA flash attention (R12, unchanged): 64x64 tiles, 512 threads / 16 warps.
// ---------------------------------------------------------------------------
#define FTP 136
#define PP  72
#define SSP 68

#define OFF_QH 0
#define OFF_QL 17408
#define OFF_KH 34816
#define OFF_KL 52224
#define OFF_VH 69632
#define OFF_VL 87040
#define OFF_SS 104448
#define OFF_PH 121856
#define OFF_PL 131072
#define OFF_RF 140288
#define OFF_RL 140544
#define FA_SMEM_BYTES 140800

__global__ __launch_bounds__(512) void flash_tc(
    const float* __restrict__ q, const float* __restrict__ k,
    const float* __restrict__ v, float* __restrict__ ctx)
{
    extern __shared__ char smc[];
    __nv_bfloat16* Qh = (__nv_bfloat16*)(smc + OFF_QH);
    __nv_bfloat16* Ql = (__nv_bfloat16*)(smc + OFF_QL);
    __nv_bfloat16* Kh = (__nv_bfloat16*)(smc + OFF_KH);
    __nv_bfloat16* Kl = (__nv_bfloat16*)(smc + OFF_KL);
    __nv_bfloat16* Vh = (__nv_bfloat16*)(smc + OFF_VH);
    __nv_bfloat16* Vl = (__nv_bfloat16*)(smc + OFF_VL);
    float* Ss = (float*)(smc + OFF_SS);
    __nv_bfloat16* Ph = (__nv_bfloat16*)(smc + OFF_PH);
    __nv_bfloat16* Pl = (__nv_bfloat16*)(smc + OFF_PL);
    float* rowfac = (float*)(smc + OFF_RF);
    float* rowl   = (float*)(smc + OFF_RL);

    const int qt = blockIdx.x;
    const int h  = blockIdx.y;
    const int b  = blockIdx.z;
    const int t  = threadIdx.x;
    const int lane = t & 31;
    const int warp = t >> 5;
    const int wm = warp >> 2;
    const int wn = warp & 3;
    const int q0 = qt * 64;
    const size_t base_bh = (size_t)b * SS * DD + (size_t)h * HD;

    const int lm_r = (lane & 7) + ((lane >> 3) & 1) * 8;
    const int lm_c = (lane >> 4) * 8;
    const int frow = lane >> 2;
    const int fcol = (lane & 3) * 2;
    const int r = t >> 3;
    const int g = t & 7;

    for (int e = t; e < 2048; e += 512) {
        int row = e >> 5;
        int c4  = (e & 31) * 4;
        float4 val = *(const float4*)(q + base_bh + (size_t)(q0 + row) * DD + c4);
        uint32_t hi2[2];
        uint32_t lo2[2];
        split4(val, hi2, lo2);
        *(uint2*)(Qh + row * FTP + c4) = make_uint2(hi2[0], hi2[1]);
        *(uint2*)(Ql + row * FTP + c4) = make_uint2(lo2[0], lo2[1]);
    }

    float m_run = -1e30f;
    float l_run = 0.f;
    float ot[4][4];
#pragma unroll
    for (int nt = 0; nt < 4; nt++)
#pragma unroll
        for (int c = 0; c < 4; c++) ot[nt][c] = 0.f;

    const float scale = 0.088388347648318447f;

    for (int kt = 0; kt <= qt; kt++) {
        __syncthreads();
        for (int e = t; e < 2048; e += 512) {
            int row = e >> 5;
            int c4  = (e & 31) * 4;
            size_t gidx = base_bh + (size_t)(kt * 64 + row) * DD + c4;
            uint32_t hi2[2];
            uint32_t lo2[2];
            float4 kv4 = *(const float4*)(k + gidx);
            split4(kv4, hi2, lo2);
            *(uint2*)(Kh + row * FTP + c4) = make_uint2(hi2[0], hi2[1]);
            *(uint2*)(Kl + row * FTP + c4) = make_uint2(lo2[0], lo2[1]);
            float4 vv4 = *(const float4*)(v + gidx);
            split4(vv4, hi2, lo2);
            *(uint2*)(Vh + row * FTP + c4) = make_uint2(hi2[0], hi2[1]);
            *(uint2*)(Vl + row * FTP + c4) = make_uint2(lo2[0], lo2[1]);
        }
        __syncthreads();

        float sa[2][4];
#pragma unroll
        for (int nt = 0; nt < 2; nt++)
#pragma unroll
            for (int c = 0; c < 4; c++) sa[nt][c] = 0.f;

        const int arow = (wm * 16 + lm_r) * FTP;
        const int brow = (wn * 16 + lm_r) * FTP;
#pragma unroll
        for (int ks = 0; ks < 8; ks++) {
            int c0 = ks * 16 + lm_c;
            uint32_t a[4];
            uint32_t t4[4];
            uint32_t bh2[2][2];
            uint32_t bl2[2][2];
            ldsm4(a, su32(Qh + arow + c0));
            ldsm4(t4, su32(Kh + brow + c0));
            bh2[0][0] = t4[0]; bh2[0][1] = t4[2];
            bh2[1][0] = t4[1]; bh2[1][1] = t4[3];
            ldsm4(t4, su32(Kl + brow + c0));
            bl2[0][0] = t4[0]; bl2[0][1] = t4[2];
            bl2[1][0] = t4[1]; bl2[1][1] = t4[3];
            mma16816(sa[0], a, bh2[0]);
            mma16816(sa[1], a, bh2[1]);
            mma16816(sa[0], a, bl2[0]);
            mma16816(sa[1], a, bl2[1]);
            ldsm4(a, su32(Ql + arow + c0));
            mma16816(sa[0], a, bh2[0]);
            mma16816(sa[1], a, bh2[1]);
        }

        {
            int r0 = wm * 16 + frow;
            int gi0 = q0 + r0;
            int gi1 = gi0 + 8;
#pragma unroll
            for (int nt = 0; nt < 2; nt++) {
                int cc = wn * 16 + nt * 8 + fcol;
                int gj = kt * 64 + cc;
                Ss[r0 * SSP + cc]           = (gj     <= gi0) ? sa[nt][0] * scale : -1e30f;
                Ss[r0 * SSP + cc + 1]       = (gj + 1 <= gi0) ? sa[nt][1] * scale : -1e30f;
                Ss[(r0 + 8) * SSP + cc]     = (gj     <= gi1) ? sa[nt][2] * scale : -1e30f;
                Ss[(r0 + 8) * SSP + cc + 1] = (gj + 1 <= gi1) ? sa[nt][3] * scale : -1e30f;
            }
        }
        __syncthreads();

        {
            float mt = -1e30f;
#pragma unroll
            for (int j = 0; j < 8; j++)
                mt = fmaxf(mt, Ss[r * SSP + g + j * 8]);
            mt = fmaxf(mt, __shfl_xor_sync(0xffffffffu, mt, 1));
            mt = fmaxf(mt, __shfl_xor_sync(0xffffffffu, mt, 2));
            mt = fmaxf(mt, __shfl_xor_sync(0xffffffffu, mt, 4));
            float m_new  = fmaxf(m_run, mt);
            float factor = __expf(m_run - m_new);
            float lsum = 0.f;
#pragma unroll
            for (int j = 0; j < 8; j++) {
                int cc = g + j * 8;
                float p = __expf(Ss[r * SSP + cc] - m_new);
                lsum += p;
                __nv_bfloat16 ph = __float2bfloat16(p);
                __nv_bfloat16 pl = __float2bfloat16(p - __bfloat162float(ph));
                Ph[r * PP + cc] = ph;
                Pl[r * PP + cc] = pl;
            }
            lsum += __shfl_xor_sync(0xffffffffu, lsum, 1);
            lsum += __shfl_xor_sync(0xffffffffu, lsum, 2);
            lsum += __shfl_xor_sync(0xffffffffu, lsum, 4);
            l_run = l_run * factor + lsum;
            m_run = m_new;
            if (g == 0) rowfac[r] = factor;
        }
        __syncthreads();

        {
            float f0 = rowfac[wm * 16 + frow];
            float f1 = rowfac[wm * 16 + frow + 8];
#pragma unroll
            for (int nt = 0; nt < 4; nt++) {
                ot[nt][0] *= f0; ot[nt][1] *= f0;
                ot[nt][2] *= f1; ot[nt][3] *= f1;
            }
        }

        const int prow = (wm * 16 + lm_r) * PP;
#pragma unroll
        for (int ks = 0; ks < 4; ks++) {
            int c0 = ks * 16 + lm_c;
            int vrow = (ks * 16 + lm_r) * FTP;
            uint32_t a[4];
            uint32_t t4[4];
            uint32_t bv[4][2];
            uint32_t bw[4][2];
            ldsm4(a, su32(Ph + prow + c0));
            ldsm4t(t4, su32(Vh + vrow + wn * 32 + lm_c));
            bv[0][0] = t4[0]; bv[0][1] = t4[1];
            bv[1][0] = t4[2]; bv[1][1] = t4[3];
            ldsm4t(t4, su32(Vh + vrow + wn * 32 + 16 + lm_c));
            bv[2][0] = t4[0]; bv[2][1] = t4[1];
            bv[3][0] = t4[2]; bv[3][1] = t4[3];
            ldsm4t(t4, su32(Vl + vrow + wn * 32 + lm_c));
            bw[0][0] = t4[0]; bw[0][1] = t4[1];
            bw[1][0] = t4[2]; bw[1][1] = t4[3];
            ldsm4t(t4, su32(Vl + vrow + wn * 32 + 16 + lm_c));
            bw[2][0] = t4[0]; bw[2][1] = t4[1];
            bw[3][0] = t4[2]; bw[3][1] = t4[3];
#pragma unroll
            for (int nt = 0; nt < 4; nt++) {
                mma16816(ot[nt], a, bv[nt]);
                mma16816(ot[nt], a, bw[nt]);
            }
            ldsm4(a, su32(Pl + prow + c0));
#pragma unroll
            for (int nt = 0; nt < 4; nt++)
                mma16816(ot[nt], a, bv[nt]);
        }
    }

    if (g == 0) rowl[r] = l_run;
    __syncthreads();

    {
        int r0 = wm * 16 + frow;
        float il0 = 1.f / rowl[r0];
        float il1 = 1.f / rowl[r0 + 8];
        float* o0 = ctx + base_bh + (size_t)(q0 + r0) * DD;
        float* o1 = ctx + base_bh + (size_t)(q0 + r0 + 8) * DD;
#pragma unroll
        for (int nt = 0; nt < 4; nt++) {
            int cc = wn * 32 + nt * 8 + fcol;
            float2 a2;
            float2 b2;
            a2.x = ot[nt][0] * il0; a2.y = ot[nt][1] * il0;
            b2.x = ot[nt][2] * il1; b2.y = ot[nt][3] * il1;
            *(float2*)(o0 + cc) = a2;
            *(float2*)(o1 + cc) = b2;
        }
    }
}

// ---------------------------------------------------------------------------
// Launch
// ---------------------------------------------------------------------------
static void split_launch(const float* src, __nv_bfloat16* hi,
                         __nv_bfloat16* lo, size_t n)
{
    int n4 = (int)(n / 4);
    split_kernel<<<(n4 + 255) / 256, 256>>>(src, hi, lo, n4);
}

extern "C" void kernel_launch(void* const* d_in, const int* in_sizes, int n_in,
                              void* d_out, int out_size)
{
    const float* x    = (const float*)d_in[0];
    const float* wq   = (const float*)d_in[1];
    const float* wdkv = (const float*)d_in[2];
    const float* wuk  = (const float*)d_in[3];
    const float* wuv  = (const float*)d_in[4];
    const float* wo   = (const float*)d_in[5];
    const float* bo   = (const float*)d_in[6];
    float* out = (float*)d_out;

    float *qb, *kb, *vb, *ctxb, *latb;
    cudaGetSymbolAddress((void**)&qb,   g_q);
    cudaGetSymbolAddress((void**)&kb,   g_k);
    cudaGetSymbolAddress((void**)&vb,   g_v);
    cudaGetSymbolAddress((void**)&ctxb, g_ctx);
    cudaGetSymbolAddress((void**)&latb, g_latent);

    __nv_bfloat16 *xh, *xl, *wqh, *wql, *wdh, *wdl, *wukh, *wukl;
    __nv_bfloat16 *wuvh, *wuvl, *woh, *wol, *lath, *latl, *ctxh, *ctxl;
    cudaGetSymbolAddress((void**)&xh,   g_x_hi);
    cudaGetSymbolAddress((void**)&xl,   g_x_lo);
    cudaGetSymbolAddress((void**)&wqh,  g_wq_hi);
    cudaGetSymbolAddress((void**)&wql,  g_wq_lo);
    cudaGetSymbolAddress((void**)&wdh,  g_wdkv_hi);
    cudaGetSymbolAddress((void**)&wdl,  g_wdkv_lo);
    cudaGetSymbolAddress((void**)&wukh, g_wuk_hi);
    cudaGetSymbolAddress((void**)&wukl, g_wuk_lo);
    cudaGetSymbolAddress((void**)&wuvh, g_wuv_hi);
    cudaGetSymbolAddress((void**)&wuvl, g_wuv_lo);
    cudaGetSymbolAddress((void**)&woh,  g_wo_hi);
    cudaGetSymbolAddress((void**)&wol,  g_wo_lo);
    cudaGetSymbolAddress((void**)&lath, g_lat_hi);
    cudaGetSymbolAddress((void**)&latl, g_lat_lo);
    cudaGetSymbolAddress((void**)&ctxh, g_ctx_hi);
    cudaGetSymbolAddress((void**)&ctxl, g_ctx_lo);

    cudaFuncSetAttribute(flash_tc,
                         cudaFuncAttributeMaxDynamicSharedMemorySize,
                         FA_SMEM_BYTES);
    cudaFuncSetAttribute(hgemm_split_nt,
                         cudaFuncAttributeMaxDynamicSharedMemorySize,
                         GEMM_SMEM_BYTES);

    split_launch(x,    xh,   xl,   (size_t)MROWS * DD);
    split_launch(wq,   wqh,  wql,  (size_t)DD * DD);
    split_launch(wdkv, wdh,  wdl,  (size_t)LL * DD);

    // q = x @ wq^T  (ncu target region)
    hgemm_split_nt<<<dim3(DD / 256, MROWS / 128), 512, GEMM_SMEM_BYTES>>>(
        xh, xl, wqh, wql, (const float*)0, qb, MROWS, DD, DD);

    split_launch(wuk, wukh, wukl, (size_t)DD * LL);
    split_launch(wuv, wuvh, wuvl, (size_t)DD * LL);
    split_launch(wo,  woh,  wol,  (size_t)DD * DD);

    // latent = x @ wdkv^T   (N=256 -> grid (1, 32))
    hgemm_split_nt<<<dim3(LL / 256, MROWS / 128), 512, GEMM_SMEM_BYTES>>>(
        xh, xl, wdh, wdl, (const float*)0, latb, MROWS, LL, DD);
    split_launch(latb, lath, latl, (size_t)MROWS * LL);

    // k = latent @ wuk^T
    hgemm_split_nt<<<dim3(DD / 256, MROWS / 128), 512, GEMM_SMEM_BYTES>>>(
        lath, latl, wukh, wukl, (const float*)0, kb, MROWS, DD, LL);
    // v = latent @ wuv^T
    hgemm_split_nt<<<dim3(DD / 256, MROWS / 128), 512, GEMM_SMEM_BYTES>>>(
        lath, latl, wuvh, wuvl, (const float*)0, vb, MROWS, DD, LL);

    // RoPE
    {
        int total = MROWS * HH * 64;
        rope_kernel<<<(total + 255) / 256, 256>>>(qb, kb);
    }

    // flash attention (tensor-core) -> ctx
    flash_tc<<<dim3(SS / 64, HH, BB), 512, FA_SMEM_BYTES>>>(qb, kb, vb, ctxb);

    // out = ctx @ wo^T + bo
    split_launch(ctxb, ctxh, ctxl, (size_t)MROWS * DD);
    hgemm_split_nt<<<dim3(DD / 256, MROWS / 128), 512, GEMM_SMEM_BYTES>>>(
        ctxh, ctxl, woh, wol, bo, out, MROWS, DD, DD);
}

// round 16
// speedup vs baseline: 1.1372x; 1.1372x over previous
#include <cuda_runtime.h>
#include <cuda_bf16.h>
#include <math.h>
#include <stdint.h>

// Problem constants: B=2, S=2048, D=2048, L=256, H=16, hd=128
#define BB   2
#define SS   2048
#define DD   2048
#define LL   256
#define HH   16
#define HD   128
#define MROWS (BB * SS)

// ---------------------------------------------------------------------------
// Scratch
// ---------------------------------------------------------------------------
__device__ float g_q[(size_t)MROWS * DD];
__device__ float g_k[(size_t)MROWS * DD];
__device__ float g_v[(size_t)MROWS * DD];

__device__ __nv_bfloat16 g_x_hi[(size_t)MROWS * DD];
__device__ __nv_bfloat16 g_x_lo[(size_t)MROWS * DD];
__device__ __nv_bfloat16 g_wq_hi[(size_t)DD * DD];
__device__ __nv_bfloat16 g_wq_lo[(size_t)DD * DD];
__device__ __nv_bfloat16 g_wdkv_hi[(size_t)LL * DD];
__device__ __nv_bfloat16 g_wdkv_lo[(size_t)LL * DD];
__device__ __nv_bfloat16 g_wuk_hi[(size_t)DD * LL];
__device__ __nv_bfloat16 g_wuk_lo[(size_t)DD * LL];
__device__ __nv_bfloat16 g_wuv_hi[(size_t)DD * LL];
__device__ __nv_bfloat16 g_wuv_lo[(size_t)DD * LL];
__device__ __nv_bfloat16 g_wo_hi[(size_t)DD * DD];
__device__ __nv_bfloat16 g_wo_lo[(size_t)DD * DD];
__device__ __nv_bfloat16 g_lat_hi[(size_t)MROWS * LL];
__device__ __nv_bfloat16 g_lat_lo[(size_t)MROWS * LL];
__device__ __nv_bfloat16 g_ctx_hi[(size_t)MROWS * DD];
__device__ __nv_bfloat16 g_ctx_lo[(size_t)MROWS * DD];

// ---------------------------------------------------------------------------
// Split fp32 -> bf16 hi + lo planes.
// ---------------------------------------------------------------------------
__global__ __launch_bounds__(256) void split_kernel(
    const float* __restrict__ src, __nv_bfloat16* __restrict__ hi,
    __nv_bfloat16* __restrict__ lo, int n4)
{
    int i = blockIdx.x * blockDim.x + threadIdx.x;
    if (i >= n4) return;
    float4 v = ((const float4*)src)[i];
    float vv[4];
    vv[0] = v.x; vv[1] = v.y; vv[2] = v.z; vv[3] = v.w;
    __nv_bfloat16 h[4];
    __nv_bfloat16 l[4];
#pragma unroll
    for (int c = 0; c < 4; c++) {
        h[c] = __float2bfloat16(vv[c]);
        l[c] = __float2bfloat16(vv[c] - __bfloat162float(h[c]));
    }
    *(uint2*)(hi + (size_t)i * 4) = *(uint2*)h;
    *(uint2*)(lo + (size_t)i * 4) = *(uint2*)l;
}

// ---------------------------------------------------------------------------
// HMMA / async helpers
// ---------------------------------------------------------------------------
__device__ __forceinline__ uint32_t su32(const void* p) {
    return (uint32_t)__cvta_generic_to_shared(p);
}
__device__ __forceinline__ void ldsm4(uint32_t* r, uint32_t a) {
    asm volatile("ldmatrix.sync.aligned.m8n8.x4.shared.b16 {%0,%1,%2,%3},[%4];"
                 : "=r"(r[0]), "=r"(r[1]), "=r"(r[2]), "=r"(r[3]) : "r"(a));
}
__device__ __forceinline__ void ldsm4t(uint32_t* r, uint32_t a) {
    asm volatile("ldmatrix.sync.aligned.m8n8.x4.trans.shared.b16 {%0,%1,%2,%3},[%4];"
                 : "=r"(r[0]), "=r"(r[1]), "=r"(r[2]), "=r"(r[3]) : "r"(a));
}
__device__ __forceinline__ void mma16816(float* d, const uint32_t* a,
                                         const uint32_t* b) {
    asm volatile(
        "mma.sync.aligned.m16n8k16.row.col.f32.bf16.bf16.f32 "
        "{%0,%1,%2,%3},{%4,%5,%6,%7},{%8,%9},{%0,%1,%2,%3};"
        : "+f"(d[0]), "+f"(d[1]), "+f"(d[2]), "+f"(d[3])
        : "r"(a[0]), "r"(a[1]), "r"(a[2]), "r"(a[3]), "r"(b[0]), "r"(b[1]));
}
__device__ __forceinline__ void cpa16(uint32_t saddr, const void* g) {
    asm volatile("cp.async.ca.shared.global [%0],[%1],16;"
                 :: "r"(saddr), "l"(g));
}
__device__ __forceinline__ void cp_commit() {
    asm volatile("cp.async.commit_group;");
}
template <int N>
__device__ __forceinline__ void cp_wait() {
    asm volatile("cp.async.wait_group %0;" :: "n"(N));
}
__device__ __forceinline__ void split4(const float4 v, uint32_t* hi2,
                                       uint32_t* lo2) {
    float f[4];
    f[0] = v.x; f[1] = v.y; f[2] = v.z; f[3] = v.w;
    __nv_bfloat16 h[4];
    __nv_bfloat16 l[4];
#pragma unroll
    for (int c = 0; c < 4; c++) {
        h[c] = __float2bfloat16(f[c]);
        l[c] = __float2bfloat16(f[c] - __bfloat162float(h[c]));
    }
    hi2[0] = *(uint32_t*)&h[0];
    hi2[1] = *(uint32_t*)&h[2];
    lo2[0] = *(uint32_t*)&l[0];
    lo2[1] = *(uint32_t*)&l[2];
}
__device__ __forceinline__ uint32_t pack_bf2(float a, float b) {
    __nv_bfloat162 p = __nv_bfloat162(__float2bfloat16(a), __float2bfloat16(b));
    return *(uint32_t*)&p;
}

// ---------------------------------------------------------------------------
// Split-bf16 GEMM (R14 config): 512 threads, 16 warps (2x8), warp tile 64x16,
// CTA 128x128, K-chunk 64. Optional fp32 output C and/or bf16 hi/lo outputs.
// ---------------------------------------------------------------------------
#define GP 72
#define PLANE (128 * GP)
#define STAGES 2
#define GEMM_SMEM_BYTES (STAGES * 4 * PLANE * 2)

__global__ __launch_bounds__(512) void hgemm_split_nt(
    const __nv_bfloat16* __restrict__ Ahi, const __nv_bfloat16* __restrict__ Alo,
    const __nv_bfloat16* __restrict__ Bhi, const __nv_bfloat16* __restrict__ Blo,
    const float* __restrict__ bias, float* __restrict__ C,
    __nv_bfloat16* __restrict__ Chi, __nv_bfloat16* __restrict__ Clo,
    int M, int N, int K)
{
    extern __shared__ __nv_bfloat16 smg[];

    const int t    = threadIdx.x;
    const int lane = t & 31;
    const int warp = t >> 5;
    const int wm   = warp >> 3;
    const int wn   = warp & 7;
    const int row0 = blockIdx.y * 128;
    const int col0 = blockIdx.x * 128;

    const int lrow = t >> 2;
    const int lk   = (t & 3) * 16;
    const __nv_bfloat16* pAh = Ahi + (size_t)(row0 + lrow) * K + lk;
    const __nv_bfloat16* pAl = Alo + (size_t)(row0 + lrow) * K + lk;
    const __nv_bfloat16* pBh = Bhi + (size_t)(col0 + lrow) * K + lk;
    const __nv_bfloat16* pBl = Blo + (size_t)(col0 + lrow) * K + lk;

    const int soff = lrow * GP + lk;
    const uint32_t smem_base = su32(smg);
    const int nkt = K / 64;

    float acc[4][2][4];
#pragma unroll
    for (int i = 0; i < 4; i++)
#pragma unroll
        for (int j = 0; j < 2; j++)
#pragma unroll
            for (int c = 0; c < 4; c++) acc[i][j][c] = 0.f;

#define FILL_STAGE(stg, ktv)                                                  \
    do {                                                                      \
        if ((ktv) < nkt) {                                                    \
            int adv = (ktv) * 64;                                             \
            uint32_t sb = smem_base + (uint32_t)(((stg) * 4) * PLANE + soff) * 2; \
            cpa16(sb,                  pAh + adv);                            \
            cpa16(sb + 16,             pAh + adv + 8);                        \
            cpa16(sb + PLANE * 2,      pAl + adv);                            \
            cpa16(sb + PLANE * 2 + 16, pAl + adv + 8);                        \
            cpa16(sb + PLANE * 4,      pBh + adv);                            \
            cpa16(sb + PLANE * 4 + 16, pBh + adv + 8);                        \
            cpa16(sb + PLANE * 6,      pBl + adv);                            \
            cpa16(sb + PLANE * 6 + 16, pBl + adv + 8);                        \
        }                                                                     \
        cp_commit();                                                          \
    } while (0)

    FILL_STAGE(0, 0);

    const int lm_r = (lane & 7) + ((lane >> 3) & 1) * 8;
    const int lm_c = (lane >> 4) * 8;

    for (int kt = 0; kt < nkt; kt++) {
        const int cur = kt & 1;
        cp_wait<0>();
        __syncthreads();

        FILL_STAGE(cur ^ 1, kt + 1);

        const __nv_bfloat16* sAh = smg + (cur * 4 + 0) * PLANE;
        const __nv_bfloat16* sAl = smg + (cur * 4 + 1) * PLANE;
        const __nv_bfloat16* sBh = smg + (cur * 4 + 2) * PLANE;
        const __nv_bfloat16* sBl = smg + (cur * 4 + 3) * PLANE;

#pragma unroll
        for (int kc = 0; kc < 4; kc++) {
            const int c0 = kc * 16 + lm_c;
            uint32_t afr[4][4];
            uint32_t bhf[2][2];
            uint32_t blf[2][2];

#pragma unroll
            for (int mt = 0; mt < 4; mt++) {
                int r = wm * 64 + mt * 16 + lm_r;
                ldsm4(afr[mt], su32(sAh + r * GP + c0));
            }
            {
                int r = wn * 16 + lm_r;
                uint32_t tmp[4];
                ldsm4(tmp, su32(sBh + r * GP + c0));
                bhf[0][0] = tmp[0]; bhf[0][1] = tmp[2];
                bhf[1][0] = tmp[1]; bhf[1][1] = tmp[3];
                ldsm4(tmp, su32(sBl + r * GP + c0));
                blf[0][0] = tmp[0]; blf[0][1] = tmp[2];
                blf[1][0] = tmp[1]; blf[1][1] = tmp[3];
            }

#pragma unroll
            for (int mt = 0; mt < 4; mt++)
#pragma unroll
                for (int nt = 0; nt < 2; nt++)
                    mma16816(acc[mt][nt], afr[mt], bhf[nt]);
#pragma unroll
            for (int mt = 0; mt < 4; mt++)
#pragma unroll
                for (int nt = 0; nt < 2; nt++)
                    mma16816(acc[mt][nt], afr[mt], blf[nt]);
#pragma unroll
            for (int mt = 0; mt < 4; mt++) {
                int r = wm * 64 + mt * 16 + lm_r;
                ldsm4(afr[mt], su32(sAl + r * GP + c0));
            }
#pragma unroll
            for (int mt = 0; mt < 4; mt++)
#pragma unroll
                for (int nt = 0; nt < 2; nt++)
                    mma16816(acc[mt][nt], afr[mt], bhf[nt]);
        }
    }

#pragma unroll
    for (int mt = 0; mt < 4; mt++) {
#pragma unroll
        for (int nt = 0; nt < 2; nt++) {
            int gr = row0 + wm * 64 + mt * 16 + (lane >> 2);
            int gc = col0 + wn * 16 + nt * 8 + (lane & 3) * 2;
            float b0 = 0.f;
            float b1 = 0.f;
            if (bias) { b0 = bias[gc]; b1 = bias[gc + 1]; }
            float v00 = acc[mt][nt][0] + b0;
            float v01 = acc[mt][nt][1] + b1;
            float v10 = acc[mt][nt][2] + b0;
            float v11 = acc[mt][nt][3] + b1;
            size_t o0 = (size_t)gr * N + gc;
            size_t o1 = (size_t)(gr + 8) * N + gc;
            if (C) {
                float2 p0; p0.x = v00; p0.y = v01;
                float2 p1; p1.x = v10; p1.y = v11;
                *(float2*)(C + o0) = p0;
                *(float2*)(C + o1) = p1;
            }
            if (Chi) {
                __nv_bfloat16 h00 = __float2bfloat16(v00);
                __nv_bfloat16 h01 = __float2bfloat16(v01);
                __nv_bfloat16 h10 = __float2bfloat16(v10);
                __nv_bfloat16 h11 = __float2bfloat16(v11);
                *(uint32_t*)(Chi + o0) = pack_bf2(v00, v01);
                *(uint32_t*)(Chi + o1) = pack_bf2(v10, v11);
                *(uint32_t*)(Clo + o0) =
                    pack_bf2(v00 - __bfloat162float(h00),
                             v01 - __bfloat162float(h01));
                *(uint32_t*)(Clo + o1) =
                    pack_bf2(v10 - __bfloat162float(h10),
                             v11 - __bfloat162float(h11));
            }
        }
    }
#undef FILL_STAGE
}

// ---------------------------------------------------------------------------
// RoPE in-place on q and k.
// ---------------------------------------------------------------------------
__global__ __launch_bounds__(256) void rope_kernel(float* __restrict__ q,
                                                   float* __restrict__ k)
{
    int idx = blockIdx.x * blockDim.x + threadIdx.x;
    const int total = MROWS * HH * 64;
    if (idx >= total) return;

    int j   = idx & 63;
    int h   = (idx >> 6) & (HH - 1);
    int row = idx >> 10;
    int s   = row & (SS - 1);

    const float LOG2_BASE = 13.287712379549449f;
    float inv = exp2f(-(float)j * (LOG2_BASE / 64.0f));
    float ang = (float)s * inv;
    float c, sn;
    sincosf(ang, &sn, &c);

    size_t base = (size_t)row * DD + h * HD;

    float q1 = q[base + j];
    float q2 = q[base + j + 64];
    q[base + j]      = q1 * c - q2 * sn;
    q[base + j + 64] = q2 * c + q1 * sn;

    float k1 = k[base + j];
    float k2 = k[base + j + 64];
    k[base + j]      = k1 * c - k2 * sn;
    k[base + j + 64] = k2 * c + k1 * sn;
}

// ---------------------------------------------------------------------------
// HMMA flash attention: 64x64 tiles, 512 threads / 16 warps.
// Epilogue writes ctx as bf16 hi/lo planes directly.
// ---------------------------------------------------------------------------
#define FTP 136
#define PP  72
#define SSP 68

#define OFF_QH 0
#define OFF_QL 17408
#define OFF_KH 34816
#define OFF_KL 52224
#define OFF_VH 69632
#define OFF_VL 87040
#define OFF_SS 104448
#define OFF_PH 121856
#define OFF_PL 131072
#define OFF_RF 140288
#define OFF_RL 140544
#define FA_SMEM_BYTES 140800

__global__ __launch_bounds__(512) void flash_tc(
    const float* __restrict__ q, const float* __restrict__ k,
    const float* __restrict__ v,
    __nv_bfloat16* __restrict__ ctx_hi, __nv_bfloat16* __restrict__ ctx_lo)
{
    extern __shared__ char smc[];
    __nv_bfloat16* Qh = (__nv_bfloat16*)(smc + OFF_QH);
    __nv_bfloat16* Ql = (__nv_bfloat16*)(smc + OFF_QL);
    __nv_bfloat16* Kh = (__nv_bfloat16*)(smc + OFF_KH);
    __nv_bfloat16* Kl = (__nv_bfloat16*)(smc + OFF_KL);
    __nv_bfloat16* Vh = (__nv_bfloat16*)(smc + OFF_VH);
    __nv_bfloat16* Vl = (__nv_bfloat16*)(smc + OFF_VL);
    float* Ss = (float*)(smc + OFF_SS);
    __nv_bfloat16* Ph = (__nv_bfloat16*)(smc + OFF_PH);
    __nv_bfloat16* Pl = (__nv_bfloat16*)(smc + OFF_PL);
    float* rowfac = (float*)(smc + OFF_RF);
    float* rowl   = (float*)(smc + OFF_RL);

    const int qt = blockIdx.x;
    const int h  = blockIdx.y;
    const int b  = blockIdx.z;
    const int t  = threadIdx.x;
    const int lane = t & 31;
    const int warp = t >> 5;
    const int wm = warp >> 2;
    const int wn = warp & 3;
    const int q0 = qt * 64;
    const size_t base_bh = (size_t)b * SS * DD + (size_t)h * HD;

    const int lm_r = (lane & 7) + ((lane >> 3) & 1) * 8;
    const int lm_c = (lane >> 4) * 8;
    const int frow = lane >> 2;
    const int fcol = (lane & 3) * 2;
    const int r = t >> 3;
    const int g = t & 7;

    for (int e = t; e < 2048; e += 512) {
        int row = e >> 5;
        int c4  = (e & 31) * 4;
        float4 val = *(const float4*)(q + base_bh + (size_t)(q0 + row) * DD + c4);
        uint32_t hi2[2];
        uint32_t lo2[2];
        split4(val, hi2, lo2);
        *(uint2*)(Qh + row * FTP + c4) = make_uint2(hi2[0], hi2[1]);
        *(uint2*)(Ql + row * FTP + c4) = make_uint2(lo2[0], lo2[1]);
    }

    float m_run = -1e30f;
    float l_run = 0.f;
    float ot[4][4];
#pragma unroll
    for (int nt = 0; nt < 4; nt++)
#pragma unroll
        for (int c = 0; c < 4; c++) ot[nt][c] = 0.f;

    const float scale = 0.088388347648318447f;

    for (int kt = 0; kt <= qt; kt++) {
        __syncthreads();
        for (int e = t; e < 2048; e += 512) {
            int row = e >> 5;
            int c4  = (e & 31) * 4;
            size_t gidx = base_bh + (size_t)(kt * 64 + row) * DD + c4;
            uint32_t hi2[2];
            uint32_t lo2[2];
            float4 kv4 = *(const float4*)(k + gidx);
            split4(kv4, hi2, lo2);
            *(uint2*)(Kh + row * FTP + c4) = make_uint2(hi2[0], hi2[1]);
            *(uint2*)(Kl + row * FTP + c4) = make_uint2(lo2[0], lo2[1]);
            float4 vv4 = *(const float4*)(v + gidx);
            split4(vv4, hi2, lo2);
            *(uint2*)(Vh + row * FTP + c4) = make_uint2(hi2[0], hi2[1]);
            *(uint2*)(Vl + row * FTP + c4) = make_uint2(lo2[0], lo2[1]);
        }
        __syncthreads();

        float sa[2][4];
#pragma unroll
        for (int nt = 0; nt < 2; nt++)
#pragma unroll
            for (int c = 0; c < 4; c++) sa[nt][c] = 0.f;

        const int arow = (wm * 16 + lm_r) * FTP;
        const int brow = (wn * 16 + lm_r) * FTP;
#pragma unroll
        for (int ks = 0; ks < 8; ks++) {
            int c0 = ks * 16 + lm_c;
            uint32_t a[4];
            uint32_t t4[4];
            uint32_t bh2[2][2];
            uint32_t bl2[2][2];
            ldsm4(a, su32(Qh + arow + c0));
            ldsm4(t4, su32(Kh + brow + c0));
            bh2[0][0] = t4[0]; bh2[0][1] = t4[2];
            bh2[1][0] = t4[1]; bh2[1][1] = t4[3];
            ldsm4(t4, su32(Kl + brow + c0));
            bl2[0][0] = t4[0]; bl2[0][1] = t4[2];
            bl2[1][0] = t4[1]; bl2[1][1] = t4[3];
            mma16816(sa[0], a, bh2[0]);
            mma16816(sa[1], a, bh2[1]);
            mma16816(sa[0], a, bl2[0]);
            mma16816(sa[1], a, bl2[1]);
            ldsm4(a, su32(Ql + arow + c0));
            mma16816(sa[0], a, bh2[0]);
            mma16816(sa[1], a, bh2[1]);
        }

        {
            int r0 = wm * 16 + frow;
            int gi0 = q0 + r0;
            int gi1 = gi0 + 8;
#pragma unroll
            for (int nt = 0; nt < 2; nt++) {
                int cc = wn * 16 + nt * 8 + fcol;
                int gj = kt * 64 + cc;
                Ss[r0 * SSP + cc]           = (gj     <= gi0) ? sa[nt][0] * scale : -1e30f;
                Ss[r0 * SSP + cc + 1]       = (gj + 1 <= gi0) ? sa[nt][1] * scale : -1e30f;
                Ss[(r0 + 8) * SSP + cc]     = (gj     <= gi1) ? sa[nt][2] * scale : -1e30f;
                Ss[(r0 + 8) * SSP + cc + 1] = (gj + 1 <= gi1) ? sa[nt][3] * scale : -1e30f;
            }
        }
        __syncthreads();

        {
            float mt = -1e30f;
#pragma unroll
            for (int j = 0; j < 8; j++)
                mt = fmaxf(mt, Ss[r * SSP + g + j * 8]);
            mt = fmaxf(mt, __shfl_xor_sync(0xffffffffu, mt, 1));
            mt = fmaxf(mt, __shfl_xor_sync(0xffffffffu, mt, 2));
            mt = fmaxf(mt, __shfl_xor_sync(0xffffffffu, mt, 4));
            float m_new  = fmaxf(m_run, mt);
            float factor = __expf(m_run - m_new);
            float lsum = 0.f;
#pragma unroll
            for (int j = 0; j < 8; j++) {
                int cc = g + j * 8;
                float p = __expf(Ss[r * SSP + cc] - m_new);
                lsum += p;
                __nv_bfloat16 ph = __float2bfloat16(p);
                __nv_bfloat16 pl = __float2bfloat16(p - __bfloat162float(ph));
                Ph[r * PP + cc] = ph;
                Pl[r * PP + cc] = pl;
            }
            lsum += __shfl_xor_sync(0xffffffffu, lsum, 1);
            lsum += __shfl_xor_sync(0xffffffffu, lsum, 2);
            lsum += __shfl_xor_sync(0xffffffffu, lsum, 4);
            l_run = l_run * factor + lsum;
            m_run = m_new;
            if (g == 0) rowfac[r] = factor;
        }
        __syncthreads();

        {
            float f0 = rowfac[wm * 16 + frow];
            float f1 = rowfac[wm * 16 + frow + 8];
#pragma unroll
            for (int nt = 0; nt < 4; nt++) {
                ot[nt][0] *= f0; ot[nt][1] *= f0;
                ot[nt][2] *= f1; ot[nt][3] *= f1;
            }
        }

        const int prow = (wm * 16 + lm_r) * PP;
#pragma unroll
        for (int ks = 0; ks < 4; ks++) {
            int c0 = ks * 16 + lm_c;
            int vrow = (ks * 16 + lm_r) * FTP;
            uint32_t a[4];
            uint32_t t4[4];
            uint32_t bv[4][2];
            uint32_t bw[4][2];
            ldsm4(a, su32(Ph + prow + c0));
            ldsm4t(t4, su32(Vh + vrow + wn * 32 + lm_c));
            bv[0][0] = t4[0]; bv[0][1] = t4[1];
            bv[1][0] = t4[2]; bv[1][1] = t4[3];
            ldsm4t(t4, su32(Vh + vrow + wn * 32 + 16 + lm_c));
            bv[2][0] = t4[0]; bv[2][1] = t4[1];
            bv[3][0] = t4[2]; bv[3][1] = t4[3];
            ldsm4t(t4, su32(Vl + vrow + wn * 32 + lm_c));
            bw[0][0] = t4[0]; bw[0][1] = t4[1];
            bw[1][0] = t4[2]; bw[1][1] = t4[3];
            ldsm4t(t4, su32(Vl + vrow + wn * 32 + 16 + lm_c));
            bw[2][0] = t4[0]; bw[2][1] = t4[1];
            bw[3][0] = t4[2]; bw[3][1] = t4[3];
#pragma unroll
            for (int nt = 0; nt < 4; nt++) {
                mma16816(ot[nt], a, bv[nt]);
                mma16816(ot[nt], a, bw[nt]);
            }
            ldsm4(a, su32(Pl + prow + c0));
#pragma unroll
            for (int nt = 0; nt < 4; nt++)
                mma16816(ot[nt], a, bv[nt]);
        }
    }

    if (g == 0) rowl[r] = l_run;
    __syncthreads();

    {
        int r0 = wm * 16 + frow;
        float il0 = 1.f / rowl[r0];
        float il1 = 1.f / rowl[r0 + 8];
        size_t ob0 = base_bh + (size_t)(q0 + r0) * DD;
        size_t ob1 = base_bh + (size_t)(q0 + r0 + 8) * DD;
#pragma unroll
        for (int nt = 0; nt < 4; nt++) {
            int cc = wn * 32 + nt * 8 + fcol;
            float a0 = ot[nt][0] * il0;
            float a1 = ot[nt][1] * il0;
            float b0 = ot[nt][2] * il1;
            float b1 = ot[nt][3] * il1;
            __nv_bfloat16 ha0 = __float2bfloat16(a0);
            __nv_bfloat16 ha1 = __float2bfloat16(a1);
            __nv_bfloat16 hb0 = __float2bfloat16(b0);
            __nv_bfloat16 hb1 = __float2bfloat16(b1);
            *(uint32_t*)(ctx_hi + ob0 + cc) = pack_bf2(a0, a1);
            *(uint32_t*)(ctx_hi + ob1 + cc) = pack_bf2(b0, b1);
            *(uint32_t*)(ctx_lo + ob0 + cc) =
                pack_bf2(a0 - __bfloat162float(ha0), a1 - __bfloat162float(ha1));
            *(uint32_t*)(ctx_lo + ob1 + cc) =
                pack_bf2(b0 - __bfloat162float(hb0), b1 - __bfloat162float(hb1));
        }
    }
}

// ---------------------------------------------------------------------------
// Launch
// ---------------------------------------------------------------------------
static void split_launch(const float* src, __nv_bfloat16* hi,
                         __nv_bfloat16* lo, size_t n)
{
    int n4 = (int)(n / 4);
    split_kernel<<<(n4 + 255) / 256, 256>>>(src, hi, lo, n4);
}

extern "C" void kernel_launch(void* const* d_in, const int* in_sizes, int n_in,
                              void* d_out, int out_size)
{
    const float* x    = (const float*)d_in[0];
    const float* wq   = (const float*)d_in[1];
    const float* wdkv = (const float*)d_in[2];
    const float* wuk  = (const float*)d_in[3];
    const float* wuv  = (const float*)d_in[4];
    const float* wo   = (const float*)d_in[5];
    const float* bo   = (const float*)d_in[6];
    float* out = (float*)d_out;

    float *qb, *kb, *vb;
    cudaGetSymbolAddress((void**)&qb, g_q);
    cudaGetSymbolAddress((void**)&kb, g_k);
    cudaGetSymbolAddress((void**)&vb, g_v);

    __nv_bfloat16 *xh, *xl, *wqh, *wql, *wdh, *wdl, *wukh, *wukl;
    __nv_bfloat16 *wuvh, *wuvl, *woh, *wol, *lath, *latl, *ctxh, *ctxl;
    cudaGetSymbolAddress((void**)&xh,   g_x_hi);
    cudaGetSymbolAddress((void**)&xl,   g_x_lo);
    cudaGetSymbolAddress((void**)&wqh,  g_wq_hi);
    cudaGetSymbolAddress((void**)&wql,  g_wq_lo);
    cudaGetSymbolAddress((void**)&wdh,  g_wdkv_hi);
    cudaGetSymbolAddress((void**)&wdl,  g_wdkv_lo);
    cudaGetSymbolAddress((void**)&wukh, g_wuk_hi);
    cudaGetSymbolAddress((void**)&wukl, g_wuk_lo);
    cudaGetSymbolAddress((void**)&wuvh, g_wuv_hi);
    cudaGetSymbolAddress((void**)&wuvl, g_wuv_lo);
    cudaGetSymbolAddress((void**)&woh,  g_wo_hi);
    cudaGetSymbolAddress((void**)&wol,  g_wo_lo);
    cudaGetSymbolAddress((void**)&lath, g_lat_hi);
    cudaGetSymbolAddress((void**)&latl, g_lat_lo);
    cudaGetSymbolAddress((void**)&ctxh, g_ctx_hi);
    cudaGetSymbolAddress((void**)&ctxl, g_ctx_lo);

    cudaFuncSetAttribute(flash_tc,
                         cudaFuncAttributeMaxDynamicSharedMemorySize,
                         FA_SMEM_BYTES);
    cudaFuncSetAttribute(hgemm_split_nt,
                         cudaFuncAttributeMaxDynamicSharedMemorySize,
                         GEMM_SMEM_BYTES);

    split_launch(x,    xh,   xl,   (size_t)MROWS * DD);
    split_launch(wq,   wqh,  wql,  (size_t)DD * DD);
    split_launch(wdkv, wdh,  wdl,  (size_t)LL * DD);

    // q = x @ wq^T  (fp32 out for flash)
    hgemm_split_nt<<<dim3(DD / 128, MROWS / 128), 512, GEMM_SMEM_BYTES>>>(
        xh, xl, wqh, wql, (const float*)0, qb,
        (__nv_bfloat16*)0, (__nv_bfloat16*)0, MROWS, DD, DD);

    split_launch(wuk, wukh, wukl, (size_t)DD * LL);
    split_launch(wuv, wuvh, wuvl, (size_t)DD * LL);
    split_launch(wo,  woh,  wol,  (size_t)DD * DD);

    // latent = x @ wdkv^T  -> hi/lo planes directly (no fp32, no split pass)
    hgemm_split_nt<<<dim3(LL / 128, MROWS / 128), 512, GEMM_SMEM_BYTES>>>(
        xh, xl, wdh, wdl, (const float*)0, (float*)0,
        lath, latl, MROWS, LL, DD);

    // k = latent @ wuk^T  (fp32 for flash)
    hgemm_split_nt<<<dim3(DD / 128, MROWS / 128), 512, GEMM_SMEM_BYTES>>>(
        lath, latl, wukh, wukl, (const float*)0, kb,
        (__nv_bfloat16*)0, (__nv_bfloat16*)0, MROWS, DD, LL);
    // v = latent @ wuv^T
    hgemm_split_nt<<<dim3(DD / 128, MROWS / 128), 512, GEMM_SMEM_BYTES>>>(
        lath, latl, wuvh, wuvl, (const float*)0, vb,
        (__nv_bfloat16*)0, (__nv_bfloat16*)0, MROWS, DD, LL);

    // RoPE
    {
        int total = MROWS * HH * 64;
        rope_kernel<<<(total + 255) / 256, 256>>>(qb, kb);
    }

    // flash attention -> ctx hi/lo planes directly
    flash_tc<<<dim3(SS / 64, HH, BB), 512, FA_SMEM_BYTES>>>(
        qb, kb, vb, ctxh, ctxl);

    // out = ctx @ wo^T + bo
    hgemm_split_nt<<<dim3(DD / 128, MROWS / 128), 512, GEMM_SMEM_BYTES>>>(
        ctxh, ctxl, woh, wol, bo, out,
        (__nv_bfloat16*)0, (__nv_bfloat16*)0, MROWS, DD, DD);
}

// round 17
// speedup vs baseline: 1.1435x; 1.0056x over previous
#include <cuda_runtime.h>
#include <cuda_bf16.h>
#include <math.h>
#include <stdint.h>

// Problem constants: B=2, S=2048, D=2048, L=256, H=16, hd=128
#define BB   2
#define SS   2048
#define DD   2048
#define LL   256
#define HH   16
#define HD   128
#define MROWS (BB * SS)

// ---------------------------------------------------------------------------
// Scratch
// ---------------------------------------------------------------------------
__device__ float g_q[(size_t)MROWS * DD];
__device__ float g_k[(size_t)MROWS * DD];
__device__ float g_v[(size_t)MROWS * DD];

__device__ __nv_bfloat16 g_x_hi[(size_t)MROWS * DD];
__device__ __nv_bfloat16 g_x_lo[(size_t)MROWS * DD];
__device__ __nv_bfloat16 g_wq_hi[(size_t)DD * DD];
__device__ __nv_bfloat16 g_wq_lo[(size_t)DD * DD];
__device__ __nv_bfloat16 g_wdkv_hi[(size_t)LL * DD];
__device__ __nv_bfloat16 g_wdkv_lo[(size_t)LL * DD];
__device__ __nv_bfloat16 g_wuk_hi[(size_t)DD * LL];
__device__ __nv_bfloat16 g_wuk_lo[(size_t)DD * LL];
__device__ __nv_bfloat16 g_wuv_hi[(size_t)DD * LL];
__device__ __nv_bfloat16 g_wuv_lo[(size_t)DD * LL];
__device__ __nv_bfloat16 g_wo_hi[(size_t)DD * DD];
__device__ __nv_bfloat16 g_wo_lo[(size_t)DD * DD];
__device__ __nv_bfloat16 g_lat_hi[(size_t)MROWS * LL];
__device__ __nv_bfloat16 g_lat_lo[(size_t)MROWS * LL];
__device__ __nv_bfloat16 g_ctx_hi[(size_t)MROWS * DD];
__device__ __nv_bfloat16 g_ctx_lo[(size_t)MROWS * DD];

// ---------------------------------------------------------------------------
// Split fp32 -> bf16 hi + lo planes.
// ---------------------------------------------------------------------------
__global__ __launch_bounds__(256) void split_kernel(
    const float* __restrict__ src, __nv_bfloat16* __restrict__ hi,
    __nv_bfloat16* __restrict__ lo, int n4)
{
    int i = blockIdx.x * blockDim.x + threadIdx.x;
    if (i >= n4) return;
    float4 v = ((const float4*)src)[i];
    float vv[4];
    vv[0] = v.x; vv[1] = v.y; vv[2] = v.z; vv[3] = v.w;
    __nv_bfloat16 h[4];
    __nv_bfloat16 l[4];
#pragma unroll
    for (int c = 0; c < 4; c++) {
        h[c] = __float2bfloat16(vv[c]);
        l[c] = __float2bfloat16(vv[c] - __bfloat162float(h[c]));
    }
    *(uint2*)(hi + (size_t)i * 4) = *(uint2*)h;
    *(uint2*)(lo + (size_t)i * 4) = *(uint2*)l;
}

// ---------------------------------------------------------------------------
// HMMA / async helpers
// ---------------------------------------------------------------------------
__device__ __forceinline__ uint32_t su32(const void* p) {
    return (uint32_t)__cvta_generic_to_shared(p);
}
__device__ __forceinline__ void ldsm4(uint32_t* r, uint32_t a) {
    asm volatile("ldmatrix.sync.aligned.m8n8.x4.shared.b16 {%0,%1,%2,%3},[%4];"
                 : "=r"(r[0]), "=r"(r[1]), "=r"(r[2]), "=r"(r[3]) : "r"(a));
}
__device__ __forceinline__ void ldsm4t(uint32_t* r, uint32_t a) {
    asm volatile("ldmatrix.sync.aligned.m8n8.x4.trans.shared.b16 {%0,%1,%2,%3},[%4];"
                 : "=r"(r[0]), "=r"(r[1]), "=r"(r[2]), "=r"(r[3]) : "r"(a));
}
__device__ __forceinline__ void mma16816(float* d, const uint32_t* a,
                                         const uint32_t* b) {
    asm volatile(
        "mma.sync.aligned.m16n8k16.row.col.f32.bf16.bf16.f32 "
        "{%0,%1,%2,%3},{%4,%5,%6,%7},{%8,%9},{%0,%1,%2,%3};"
        : "+f"(d[0]), "+f"(d[1]), "+f"(d[2]), "+f"(d[3])
        : "r"(a[0]), "r"(a[1]), "r"(a[2]), "r"(a[3]), "r"(b[0]), "r"(b[1]));
}
__device__ __forceinline__ void cpa16(uint32_t saddr, const void* g) {
    asm volatile("cp.async.ca.shared.global [%0],[%1],16;"
                 :: "r"(saddr), "l"(g));
}
__device__ __forceinline__ void cp_commit() {
    asm volatile("cp.async.commit_group;");
}
template <int N>
__device__ __forceinline__ void cp_wait() {
    asm volatile("cp.async.wait_group %0;" :: "n"(N));
}
__device__ __forceinline__ void split4(const float4 v, uint32_t* hi2,
                                       uint32_t* lo2) {
    float f[4];
    f[0] = v.x; f[1] = v.y; f[2] = v.z; f[3] = v.w;
    __nv_bfloat16 h[4];
    __nv_bfloat16 l[4];
#pragma unroll
    for (int c = 0; c < 4; c++) {
        h[c] = __float2bfloat16(f[c]);
        l[c] = __float2bfloat16(f[c] - __bfloat162float(h[c]));
    }
    hi2[0] = *(uint32_t*)&h[0];
    hi2[1] = *(uint32_t*)&h[2];
    lo2[0] = *(uint32_t*)&l[0];
    lo2[1] = *(uint32_t*)&l[2];
}
__device__ __forceinline__ uint32_t pack_bf2(float a, float b) {
    __nv_bfloat162 p = __nv_bfloat162(__float2bfloat16(a), __float2bfloat16(b));
    return *(uint32_t*)&p;
}

// ---------------------------------------------------------------------------
// Split-bf16 GEMM (R14/R16): 512 threads, 16 warps (2x8), warp tile 64x16,
// CTA 128x128, K-chunk 64. fp32 and/or bf16-plane outputs.
// ---------------------------------------------------------------------------
#define GP 72
#define PLANE (128 * GP)
#define GEMM_SMEM_BYTES (2 * 4 * PLANE * 2)

__global__ __launch_bounds__(512) void hgemm_split_nt(
    const __nv_bfloat16* __restrict__ Ahi, const __nv_bfloat16* __restrict__ Alo,
    const __nv_bfloat16* __restrict__ Bhi, const __nv_bfloat16* __restrict__ Blo,
    const float* __restrict__ bias, float* __restrict__ C,
    __nv_bfloat16* __restrict__ Chi, __nv_bfloat16* __restrict__ Clo,
    int M, int N, int K)
{
    extern __shared__ __nv_bfloat16 smg[];

    const int t    = threadIdx.x;
    const int lane = t & 31;
    const int warp = t >> 5;
    const int wm   = warp >> 3;
    const int wn   = warp & 7;
    const int row0 = blockIdx.y * 128;
    const int col0 = blockIdx.x * 128;

    const int lrow = t >> 2;
    const int lk   = (t & 3) * 16;
    const __nv_bfloat16* pAh = Ahi + (size_t)(row0 + lrow) * K + lk;
    const __nv_bfloat16* pAl = Alo + (size_t)(row0 + lrow) * K + lk;
    const __nv_bfloat16* pBh = Bhi + (size_t)(col0 + lrow) * K + lk;
    const __nv_bfloat16* pBl = Blo + (size_t)(col0 + lrow) * K + lk;

    const int soff = lrow * GP + lk;
    const uint32_t smem_base = su32(smg);
    const int nkt = K / 64;

    float acc[4][2][4];
#pragma unroll
    for (int i = 0; i < 4; i++)
#pragma unroll
        for (int j = 0; j < 2; j++)
#pragma unroll
            for (int c = 0; c < 4; c++) acc[i][j][c] = 0.f;

#define FILL_STAGE(stg, ktv)                                                  \
    do {                                                                      \
        if ((ktv) < nkt) {                                                    \
            int adv = (ktv) * 64;                                             \
            uint32_t sb = smem_base + (uint32_t)(((stg) * 4) * PLANE + soff) * 2; \
            cpa16(sb,                  pAh + adv);                            \
            cpa16(sb + 16,             pAh + adv + 8);                        \
            cpa16(sb + PLANE * 2,      pAl + adv);                            \
            cpa16(sb + PLANE * 2 + 16, pAl + adv + 8);                        \
            cpa16(sb + PLANE * 4,      pBh + adv);                            \
            cpa16(sb + PLANE * 4 + 16, pBh + adv + 8);                        \
            cpa16(sb + PLANE * 6,      pBl + adv);                            \
            cpa16(sb + PLANE * 6 + 16, pBl + adv + 8);                        \
        }                                                                     \
        cp_commit();                                                          \
    } while (0)

    FILL_STAGE(0, 0);

    const int lm_r = (lane & 7) + ((lane >> 3) & 1) * 8;
    const int lm_c = (lane >> 4) * 8;

    for (int kt = 0; kt < nkt; kt++) {
        const int cur = kt & 1;
        cp_wait<0>();
        __syncthreads();

        FILL_STAGE(cur ^ 1, kt + 1);

        const __nv_bfloat16* sAh = smg + (cur * 4 + 0) * PLANE;
        const __nv_bfloat16* sAl = smg + (cur * 4 + 1) * PLANE;
        const __nv_bfloat16* sBh = smg + (cur * 4 + 2) * PLANE;
        const __nv_bfloat16* sBl = smg + (cur * 4 + 3) * PLANE;

#pragma unroll
        for (int kc = 0; kc < 4; kc++) {
            const int c0 = kc * 16 + lm_c;
            uint32_t afr[4][4];
            uint32_t bhf[2][2];
            uint32_t blf[2][2];

#pragma unroll
            for (int mt = 0; mt < 4; mt++) {
                int r = wm * 64 + mt * 16 + lm_r;
                ldsm4(afr[mt], su32(sAh + r * GP + c0));
            }
            {
                int r = wn * 16 + lm_r;
                uint32_t tmp[4];
                ldsm4(tmp, su32(sBh + r * GP + c0));
                bhf[0][0] = tmp[0]; bhf[0][1] = tmp[2];
                bhf[1][0] = tmp[1]; bhf[1][1] = tmp[3];
                ldsm4(tmp, su32(sBl + r * GP + c0));
                blf[0][0] = tmp[0]; blf[0][1] = tmp[2];
                blf[1][0] = tmp[1]; blf[1][1] = tmp[3];
            }

#pragma unroll
            for (int mt = 0; mt < 4; mt++)
#pragma unroll
                for (int nt = 0; nt < 2; nt++)
                    mma16816(acc[mt][nt], afr[mt], bhf[nt]);
#pragma unroll
            for (int mt = 0; mt < 4; mt++)
#pragma unroll
                for (int nt = 0; nt < 2; nt++)
                    mma16816(acc[mt][nt], afr[mt], blf[nt]);
#pragma unroll
            for (int mt = 0; mt < 4; mt++) {
                int r = wm * 64 + mt * 16 + lm_r;
                ldsm4(afr[mt], su32(sAl + r * GP + c0));
            }
#pragma unroll
            for (int mt = 0; mt < 4; mt++)
#pragma unroll
                for (int nt = 0; nt < 2; nt++)
                    mma16816(acc[mt][nt], afr[mt], bhf[nt]);
        }
    }

#pragma unroll
    for (int mt = 0; mt < 4; mt++) {
#pragma unroll
        for (int nt = 0; nt < 2; nt++) {
            int gr = row0 + wm * 64 + mt * 16 + (lane >> 2);
            int gc = col0 + wn * 16 + nt * 8 + (lane & 3) * 2;
            float b0 = 0.f;
            float b1 = 0.f;
            if (bias) { b0 = bias[gc]; b1 = bias[gc + 1]; }
            float v00 = acc[mt][nt][0] + b0;
            float v01 = acc[mt][nt][1] + b1;
            float v10 = acc[mt][nt][2] + b0;
            float v11 = acc[mt][nt][3] + b1;
            size_t o0 = (size_t)gr * N + gc;
            size_t o1 = (size_t)(gr + 8) * N + gc;
            if (C) {
                float2 p0; p0.x = v00; p0.y = v01;
                float2 p1; p1.x = v10; p1.y = v11;
                *(float2*)(C + o0) = p0;
                *(float2*)(C + o1) = p1;
            }
            if (Chi) {
                __nv_bfloat16 h00 = __float2bfloat16(v00);
                __nv_bfloat16 h01 = __float2bfloat16(v01);
                __nv_bfloat16 h10 = __float2bfloat16(v10);
                __nv_bfloat16 h11 = __float2bfloat16(v11);
                *(uint32_t*)(Chi + o0) = pack_bf2(v00, v01);
                *(uint32_t*)(Chi + o1) = pack_bf2(v10, v11);
                *(uint32_t*)(Clo + o0) =
                    pack_bf2(v00 - __bfloat162float(h00),
                             v01 - __bfloat162float(h01));
                *(uint32_t*)(Clo + o1) =
                    pack_bf2(v10 - __bfloat162float(h10),
                             v11 - __bfloat162float(h11));
            }
        }
    }
#undef FILL_STAGE
}

// ---------------------------------------------------------------------------
// Fused K+V GEMM: same A (latent), two B matrices (wuk, wuv), K=256.
// 512 threads, 16 warps (2x8), warp tile 64x16 per output, CTA 128x128.
// smem per stage: A hi/lo + Bk hi/lo + Bv hi/lo = 6 planes.
// ---------------------------------------------------------------------------
#define KV_STG_ELEMS (6 * PLANE)
#define KV_SMEM_BYTES (2 * KV_STG_ELEMS * 2)    // 221184

__global__ __launch_bounds__(512) void hgemm_kv(
    const __nv_bfloat16* __restrict__ Ahi, const __nv_bfloat16* __restrict__ Alo,
    const __nv_bfloat16* __restrict__ Bkh, const __nv_bfloat16* __restrict__ Bkl,
    const __nv_bfloat16* __restrict__ Bvh, const __nv_bfloat16* __restrict__ Bvl,
    float* __restrict__ Ck, float* __restrict__ Cv,
    int M, int N, int K)
{
    extern __shared__ __nv_bfloat16 smg[];

    const int t    = threadIdx.x;
    const int lane = t & 31;
    const int warp = t >> 5;
    const int wm   = warp >> 3;
    const int wn   = warp & 7;
    const int row0 = blockIdx.y * 128;
    const int col0 = blockIdx.x * 128;

    const int lrow = t >> 2;
    const int lk   = (t & 3) * 16;
    const __nv_bfloat16* pAh = Ahi + (size_t)(row0 + lrow) * K + lk;
    const __nv_bfloat16* pAl = Alo + (size_t)(row0 + lrow) * K + lk;
    const __nv_bfloat16* pKh = Bkh + (size_t)(col0 + lrow) * K + lk;
    const __nv_bfloat16* pKl = Bkl + (size_t)(col0 + lrow) * K + lk;
    const __nv_bfloat16* pVh = Bvh + (size_t)(col0 + lrow) * K + lk;
    const __nv_bfloat16* pVl = Bvl + (size_t)(col0 + lrow) * K + lk;

    const int soff = lrow * GP + lk;
    const uint32_t smem_base = su32(smg);
    const int nkt = K / 64;

    float ak[4][2][4];
    float av[4][2][4];
#pragma unroll
    for (int i = 0; i < 4; i++)
#pragma unroll
        for (int j = 0; j < 2; j++)
#pragma unroll
            for (int c = 0; c < 4; c++) { ak[i][j][c] = 0.f; av[i][j][c] = 0.f; }

#define KV_FILL(stg, ktv)                                                     \
    do {                                                                      \
        if ((ktv) < nkt) {                                                    \
            int adv = (ktv) * 64;                                             \
            uint32_t sb = smem_base + (uint32_t)((stg) * KV_STG_ELEMS + soff) * 2; \
            cpa16(sb,                  pAh + adv);                            \
            cpa16(sb + 16,             pAh + adv + 8);                        \
            cpa16(sb + PLANE * 2,      pAl + adv);                            \
            cpa16(sb + PLANE * 2 + 16, pAl + adv + 8);                        \
            cpa16(sb + PLANE * 4,      pKh + adv);                            \
            cpa16(sb + PLANE * 4 + 16, pKh + adv + 8);                        \
            cpa16(sb + PLANE * 6,      pKl + adv);                            \
            cpa16(sb + PLANE * 6 + 16, pKl + adv + 8);                        \
            cpa16(sb + PLANE * 8,      pVh + adv);                            \
            cpa16(sb + PLANE * 8 + 16, pVh + adv + 8);                        \
            cpa16(sb + PLANE * 10,     pVl + adv);                            \
            cpa16(sb + PLANE * 10 + 16,pVl + adv + 8);                        \
        }                                                                     \
        cp_commit();                                                          \
    } while (0)

    KV_FILL(0, 0);

    const int lm_r = (lane & 7) + ((lane >> 3) & 1) * 8;
    const int lm_c = (lane >> 4) * 8;

    for (int kt = 0; kt < nkt; kt++) {
        const int cur = kt & 1;
        cp_wait<0>();
        __syncthreads();

        KV_FILL(cur ^ 1, kt + 1);

        const __nv_bfloat16* sAh = smg + cur * KV_STG_ELEMS;
        const __nv_bfloat16* sAl = sAh + PLANE;
        const __nv_bfloat16* sKh = sAh + 2 * PLANE;
        const __nv_bfloat16* sKl = sAh + 3 * PLANE;
        const __nv_bfloat16* sVh = sAh + 4 * PLANE;
        const __nv_bfloat16* sVl = sAh + 5 * PLANE;

#pragma unroll
        for (int kc = 0; kc < 4; kc++) {
            const int c0 = kc * 16 + lm_c;
            uint32_t ah[4][4];
            uint32_t al[4][4];
            uint32_t bh[2][2];
            uint32_t bl[2][2];

#pragma unroll
            for (int mt = 0; mt < 4; mt++) {
                int r = wm * 64 + mt * 16 + lm_r;
                ldsm4(ah[mt], su32(sAh + r * GP + c0));
                ldsm4(al[mt], su32(sAl + r * GP + c0));
            }
            const int brow = (wn * 16 + lm_r) * GP + c0;
            // ---- K output ----
            {
                uint32_t tmp[4];
                ldsm4(tmp, su32(sKh + brow));
                bh[0][0] = tmp[0]; bh[0][1] = tmp[2];
                bh[1][0] = tmp[1]; bh[1][1] = tmp[3];
                ldsm4(tmp, su32(sKl + brow));
                bl[0][0] = tmp[0]; bl[0][1] = tmp[2];
                bl[1][0] = tmp[1]; bl[1][1] = tmp[3];
            }
#pragma unroll
            for (int mt = 0; mt < 4; mt++)
#pragma unroll
                for (int nt = 0; nt < 2; nt++) {
                    mma16816(ak[mt][nt], ah[mt], bh[nt]);
                    mma16816(ak[mt][nt], ah[mt], bl[nt]);
                    mma16816(ak[mt][nt], al[mt], bh[nt]);
                }
            // ---- V output ----
            {
                uint32_t tmp[4];
                ldsm4(tmp, su32(sVh + brow));
                bh[0][0] = tmp[0]; bh[0][1] = tmp[2];
                bh[1][0] = tmp[1]; bh[1][1] = tmp[3];
                ldsm4(tmp, su32(sVl + brow));
                bl[0][0] = tmp[0]; bl[0][1] = tmp[2];
                bl[1][0] = tmp[1]; bl[1][1] = tmp[3];
            }
#pragma unroll
            for (int mt = 0; mt < 4; mt++)
#pragma unroll
                for (int nt = 0; nt < 2; nt++) {
                    mma16816(av[mt][nt], ah[mt], bh[nt]);
                    mma16816(av[mt][nt], ah[mt], bl[nt]);
                    mma16816(av[mt][nt], al[mt], bh[nt]);
                }
        }
    }

#pragma unroll
    for (int mt = 0; mt < 4; mt++) {
#pragma unroll
        for (int nt = 0; nt < 2; nt++) {
            int gr = row0 + wm * 64 + mt * 16 + (lane >> 2);
            int gc = col0 + wn * 16 + nt * 8 + (lane & 3) * 2;
            size_t o0 = (size_t)gr * N + gc;
            size_t o1 = (size_t)(gr + 8) * N + gc;
            float2 p;
            p.x = ak[mt][nt][0]; p.y = ak[mt][nt][1];
            *(float2*)(Ck + o0) = p;
            p.x = ak[mt][nt][2]; p.y = ak[mt][nt][3];
            *(float2*)(Ck + o1) = p;
            p.x = av[mt][nt][0]; p.y = av[mt][nt][1];
            *(float2*)(Cv + o0) = p;
            p.x = av[mt][nt][2]; p.y = av[mt][nt][3];
            *(float2*)(Cv + o1) = p;
        }
    }
#undef KV_FILL
}

// ---------------------------------------------------------------------------
// RoPE in-place on q and k.
// ---------------------------------------------------------------------------
__global__ __launch_bounds__(256) void rope_kernel(float* __restrict__ q,
                                                   float* __restrict__ k)
{
    int idx = blockIdx.x * blockDim.x + threadIdx.x;
    const int total = MROWS * HH * 64;
    if (idx >= total) return;

    int j   = idx & 63;
    int h   = (idx >> 6) & (HH - 1);
    int row = idx >> 10;
    int s   = row & (SS - 1);

    const float LOG2_BASE = 13.287712379549449f;
    float inv = exp2f(-(float)j * (LOG2_BASE / 64.0f));
    float ang = (float)s * inv;
    float c, sn;
    sincosf(ang, &sn, &c);

    size_t base = (size_t)row * DD + h * HD;

    float q1 = q[base + j];
    float q2 = q[base + j + 64];
    q[base + j]      = q1 * c - q2 * sn;
    q[base + j + 64] = q2 * c + q1 * sn;

    float k1 = k[base + j];
    float k2 = k[base + j + 64];
    k[base + j]      = k1 * c - k2 * sn;
    k[base + j + 64] = k2 * c + k1 * sn;
}

// ---------------------------------------------------------------------------
// HMMA flash attention: 64x64 tiles, 512 threads / 16 warps.
// Epilogue writes ctx as bf16 hi/lo planes directly.
// ---------------------------------------------------------------------------
#define FTP 136
#define PP  72
#define SSP 68

#define OFF_QH 0
#define OFF_QL 17408
#define OFF_KH 34816
#define OFF_KL 52224
#define OFF_VH 69632
#define OFF_VL 87040
#define OFF_SS 104448
#define OFF_PH 121856
#define OFF_PL 131072
#define OFF_RF 140288
#define OFF_RL 140544
#define FA_SMEM_BYTES 140800

__global__ __launch_bounds__(512) void flash_tc(
    const float* __restrict__ q, const float* __restrict__ k,
    const float* __restrict__ v,
    __nv_bfloat16* __restrict__ ctx_hi, __nv_bfloat16* __restrict__ ctx_lo)
{
    extern __shared__ char smc[];
    __nv_bfloat16* Qh = (__nv_bfloat16*)(smc + OFF_QH);
    __nv_bfloat16* Ql = (__nv_bfloat16*)(smc + OFF_QL);
    __nv_bfloat16* Kh = (__nv_bfloat16*)(smc + OFF_KH);
    __nv_bfloat16* Kl = (__nv_bfloat16*)(smc + OFF_KL);
    __nv_bfloat16* Vh = (__nv_bfloat16*)(smc + OFF_VH);
    __nv_bfloat16* Vl = (__nv_bfloat16*)(smc + OFF_VL);
    float* Ss = (float*)(smc + OFF_SS);
    __nv_bfloat16* Ph = (__nv_bfloat16*)(smc + OFF_PH);
    __nv_bfloat16* Pl = (__nv_bfloat16*)(smc + OFF_PL);
    float* rowfac = (float*)(smc + OFF_RF);
    float* rowl   = (float*)(smc + OFF_RL);

    const int qt = blockIdx.x;
    const int h  = blockIdx.y;
    const int b  = blockIdx.z;
    const int t  = threadIdx.x;
    const int lane = t & 31;
    const int warp = t >> 5;
    const int wm = warp >> 2;
    const int wn = warp & 3;
    const int q0 = qt * 64;
    const size_t base_bh = (size_t)b * SS * DD + (size_t)h * HD;

    const int lm_r = (lane & 7) + ((lane >> 3) & 1) * 8;
    const int lm_c = (lane >> 4) * 8;
    const int frow = lane >> 2;
    const int fcol = (lane & 3) * 2;
    const int r = t >> 3;
    const int g = t & 7;

    for (int e = t; e < 2048; e += 512) {
        int row = e >> 5;
        int c4  = (e & 31) * 4;
        float4 val = *(const float4*)(q + base_bh + (size_t)(q0 + row) * DD + c4);
        uint32_t hi2[2];
        uint32_t lo2[2];
        split4(val, hi2, lo2);
        *(uint2*)(Qh + row * FTP + c4) = make_uint2(hi2[0], hi2[1]);
        *(uint2*)(Ql + row * FTP + c4) = make_uint2(lo2[0], lo2[1]);
    }

    float m_run = -1e30f;
    float l_run = 0.f;
    float ot[4][4];
#pragma unroll
    for (int nt = 0; nt < 4; nt++)
#pragma unroll
        for (int c = 0; c < 4; c++) ot[nt][c] = 0.f;

    const float scale = 0.088388347648318447f;

    for (int kt = 0; kt <= qt; kt++) {
        __syncthreads();
        for (int e = t; e < 2048; e += 512) {
            int row = e >> 5;
            int c4  = (e & 31) * 4;
            size_t gidx = base_bh + (size_t)(kt * 64 + row) * DD + c4;
            uint32_t hi2[2];
            uint32_t lo2[2];
            float4 kv4 = *(const float4*)(k + gidx);
            split4(kv4, hi2, lo2);
            *(uint2*)(Kh + row * FTP + c4) = make_uint2(hi2[0], hi2[1]);
            *(uint2*)(Kl + row * FTP + c4) = make_uint2(lo2[0], lo2[1]);
            float4 vv4 = *(const float4*)(v + gidx);
            split4(vv4, hi2, lo2);
            *(uint2*)(Vh + row * FTP + c4) = make_uint2(hi2[0], hi2[1]);
            *(uint2*)(Vl + row * FTP + c4) = make_uint2(lo2[0], lo2[1]);
        }
        __syncthreads();

        float sa[2][4];
#pragma unroll
        for (int nt = 0; nt < 2; nt++)
#pragma unroll
            for (int c = 0; c < 4; c++) sa[nt][c] = 0.f;

        const int arow = (wm * 16 + lm_r) * FTP;
        const int brow = (wn * 16 + lm_r) * FTP;
#pragma unroll
        for (int ks = 0; ks < 8; ks++) {
            int c0 = ks * 16 + lm_c;
            uint32_t a[4];
            uint32_t t4[4];
            uint32_t bh2[2][2];
            uint32_t bl2[2][2];
            ldsm4(a, su32(Qh + arow + c0));
            ldsm4(t4, su32(Kh + brow + c0));
            bh2[0][0] = t4[0]; bh2[0][1] = t4[2];
            bh2[1][0] = t4[1]; bh2[1][1] = t4[3];
            ldsm4(t4, su32(Kl + brow + c0));
            bl2[0][0] = t4[0]; bl2[0][1] = t4[2];
            bl2[1][0] = t4[1]; bl2[1][1] = t4[3];
            mma16816(sa[0], a, bh2[0]);
            mma16816(sa[1], a, bh2[1]);
            mma16816(sa[0], a, bl2[0]);
            mma16816(sa[1], a, bl2[1]);
            ldsm4(a, su32(Ql + arow + c0));
            mma16816(sa[0], a, bh2[0]);
            mma16816(sa[1], a, bh2[1]);
        }

        {
            int r0 = wm * 16 + frow;
            int gi0 = q0 + r0;
            int gi1 = gi0 + 8;
#pragma unroll
            for (int nt = 0; nt < 2; nt++) {
                int cc = wn * 16 + nt * 8 + fcol;
                int gj = kt * 64 + cc;
                Ss[r0 * SSP + cc]           = (gj     <= gi0) ? sa[nt][0] * scale : -1e30f;
                Ss[r0 * SSP + cc + 1]       = (gj + 1 <= gi0) ? sa[nt][1] * scale : -1e30f;
                Ss[(r0 + 8) * SSP + cc]     = (gj     <= gi1) ? sa[nt][2] * scale : -1e30f;
                Ss[(r0 + 8) * SSP + cc + 1] = (gj + 1 <= gi1) ? sa[nt][3] * scale : -1e30f;
            }
        }
        __syncthreads();

        {
            float mt = -1e30f;
#pragma unroll
            for (int j = 0; j < 8; j++)
                mt = fmaxf(mt, Ss[r * SSP + g + j * 8]);
            mt = fmaxf(mt, __shfl_xor_sync(0xffffffffu, mt, 1));
            mt = fmaxf(mt, __shfl_xor_sync(0xffffffffu, mt, 2));
            mt = fmaxf(mt, __shfl_xor_sync(0xffffffffu, mt, 4));
            float m_new  = fmaxf(m_run, mt);
            float factor = __expf(m_run - m_new);
            float lsum = 0.f;
#pragma unroll
            for (int j = 0; j < 8; j++) {
                int cc = g + j * 8;
                float p = __expf(Ss[r * SSP + cc] - m_new);
                lsum += p;
                __nv_bfloat16 ph = __float2bfloat16(p);
                __nv_bfloat16 pl = __float2bfloat16(p - __bfloat162float(ph));
                Ph[r * PP + cc] = ph;
                Pl[r * PP + cc] = pl;
            }
            lsum += __shfl_xor_sync(0xffffffffu, lsum, 1);
            lsum += __shfl_xor_sync(0xffffffffu, lsum, 2);
            lsum += __shfl_xor_sync(0xffffffffu, lsum, 4);
            l_run = l_run * factor + lsum;
            m_run = m_new;
            if (g == 0) rowfac[r] = factor;
        }
        __syncthreads();

        {
            float f0 = rowfac[wm * 16 + frow];
            float f1 = rowfac[wm * 16 + frow + 8];
#pragma unroll
            for (int nt = 0; nt < 4; nt++) {
                ot[nt][0] *= f0; ot[nt][1] *= f0;
                ot[nt][2] *= f1; ot[nt][3] *= f1;
            }
        }

        const int prow = (wm * 16 + lm_r) * PP;
#pragma unroll
        for (int ks = 0; ks < 4; ks++) {
            int c0 = ks * 16 + lm_c;
            int vrow = (ks * 16 + lm_r) * FTP;
            uint32_t a[4];
            uint32_t t4[4];
            uint32_t bv[4][2];
            uint32_t bw[4][2];
            ldsm4(a, su32(Ph + prow + c0));
            ldsm4t(t4, su32(Vh + vrow + wn * 32 + lm_c));
            bv[0][0] = t4[0]; bv[0][1] = t4[1];
            bv[1][0] = t4[2]; bv[1][1] = t4[3];
            ldsm4t(t4, su32(Vh + vrow + wn * 32 + 16 + lm_c));
            bv[2][0] = t4[0]; bv[2][1] = t4[1];
            bv[3][0] = t4[2]; bv[3][1] = t4[3];
            ldsm4t(t4, su32(Vl + vrow + wn * 32 + lm_c));
            bw[0][0] = t4[0]; bw[0][1] = t4[1];
            bw[1][0] = t4[2]; bw[1][1] = t4[3];
            ldsm4t(t4, su32(Vl + vrow + wn * 32 + 16 + lm_c));
            bw[2][0] = t4[0]; bw[2][1] = t4[1];
            bw[3][0] = t4[2]; bw[3][1] = t4[3];
#pragma unroll
            for (int nt = 0; nt < 4; nt++) {
                mma16816(ot[nt], a, bv[nt]);
                mma16816(ot[nt], a, bw[nt]);
            }
            ldsm4(a, su32(Pl + prow + c0));
#pragma unroll
            for (int nt = 0; nt < 4; nt++)
                mma16816(ot[nt], a, bv[nt]);
        }
    }

    if (g == 0) rowl[r] = l_run;
    __syncthreads();

    {
        int r0 = wm * 16 + frow;
        float il0 = 1.f / rowl[r0];
        float il1 = 1.f / rowl[r0 + 8];
        size_t ob0 = base_bh + (size_t)(q0 + r0) * DD;
        size_t ob1 = base_bh + (size_t)(q0 + r0 + 8) * DD;
#pragma unroll
        for (int nt = 0; nt < 4; nt++) {
            int cc = wn * 32 + nt * 8 + fcol;
            float a0 = ot[nt][0] * il0;
            float a1 = ot[nt][1] * il0;
            float b0 = ot[nt][2] * il1;
            float b1 = ot[nt][3] * il1;
            __nv_bfloat16 ha0 = __float2bfloat16(a0);
            __nv_bfloat16 ha1 = __float2bfloat16(a1);
            __nv_bfloat16 hb0 = __float2bfloat16(b0);
            __nv_bfloat16 hb1 = __float2bfloat16(b1);
            *(uint32_t*)(ctx_hi + ob0 + cc) = pack_bf2(a0, a1);
            *(uint32_t*)(ctx_hi + ob1 + cc) = pack_bf2(b0, b1);
            *(uint32_t*)(ctx_lo + ob0 + cc) =
                pack_bf2(a0 - __bfloat162float(ha0), a1 - __bfloat162float(ha1));
            *(uint32_t*)(ctx_lo + ob1 + cc) =
                pack_bf2(b0 - __bfloat162float(hb0), b1 - __bfloat162float(hb1));
        }
    }
}

// ---------------------------------------------------------------------------
// Launch
// ---------------------------------------------------------------------------
static void split_launch(const float* src, __nv_bfloat16* hi,
                         __nv_bfloat16* lo, size_t n)
{
    int n4 = (int)(n / 4);
    split_kernel<<<(n4 + 255) / 256, 256>>>(src, hi, lo, n4);
}

extern "C" void kernel_launch(void* const* d_in, const int* in_sizes, int n_in,
                              void* d_out, int out_size)
{
    const float* x    = (const float*)d_in[0];
    const float* wq   = (const float*)d_in[1];
    const float* wdkv = (const float*)d_in[2];
    const float* wuk  = (const float*)d_in[3];
    const float* wuv  = (const float*)d_in[4];
    const float* wo   = (const float*)d_in[5];
    const float* bo   = (const float*)d_in[6];
    float* out = (float*)d_out;

    float *qb, *kb, *vb;
    cudaGetSymbolAddress((void**)&qb, g_q);
    cudaGetSymbolAddress((void**)&kb, g_k);
    cudaGetSymbolAddress((void**)&vb, g_v);

    __nv_bfloat16 *xh, *xl, *wqh, *wql, *wdh, *wdl, *wukh, *wukl;
    __nv_bfloat16 *wuvh, *wuvl, *woh, *wol, *lath, *latl, *ctxh, *ctxl;
    cudaGetSymbolAddress((void**)&xh,   g_x_hi);
    cudaGetSymbolAddress((void**)&xl,   g_x_lo);
    cudaGetSymbolAddress((void**)&wqh,  g_wq_hi);
    cudaGetSymbolAddress((void**)&wql,  g_wq_lo);
    cudaGetSymbolAddress((void**)&wdh,  g_wdkv_hi);
    cudaGetSymbolAddress((void**)&wdl,  g_wdkv_lo);
    cudaGetSymbolAddress((void**)&wukh, g_wuk_hi);
    cudaGetSymbolAddress((void**)&wukl, g_wuk_lo);
    cudaGetSymbolAddress((void**)&wuvh, g_wuv_hi);
    cudaGetSymbolAddress((void**)&wuvl, g_wuv_lo);
    cudaGetSymbolAddress((void**)&woh,  g_wo_hi);
    cudaGetSymbolAddress((void**)&wol,  g_wo_lo);
    cudaGetSymbolAddress((void**)&lath, g_lat_hi);
    cudaGetSymbolAddress((void**)&latl, g_lat_lo);
    cudaGetSymbolAddress((void**)&ctxh, g_ctx_hi);
    cudaGetSymbolAddress((void**)&ctxl, g_ctx_lo);

    cudaFuncSetAttribute(flash_tc,
                         cudaFuncAttributeMaxDynamicSharedMemorySize,
                         FA_SMEM_BYTES);
    cudaFuncSetAttribute(hgemm_split_nt,
                         cudaFuncAttributeMaxDynamicSharedMemorySize,
                         GEMM_SMEM_BYTES);
    cudaFuncSetAttribute(hgemm_kv,
                         cudaFuncAttributeMaxDynamicSharedMemorySize,
                         KV_SMEM_BYTES);

    split_launch(x,    xh,   xl,   (size_t)MROWS * DD);
    split_launch(wq,   wqh,  wql,  (size_t)DD * DD);
    split_launch(wdkv, wdh,  wdl,  (size_t)LL * DD);

    // q = x @ wq^T  (fp32 out for flash)
    hgemm_split_nt<<<dim3(DD / 128, MROWS / 128), 512, GEMM_SMEM_BYTES>>>(
        xh, xl, wqh, wql, (const float*)0, qb,
        (__nv_bfloat16*)0, (__nv_bfloat16*)0, MROWS, DD, DD);

    split_launch(wuk, wukh, wukl, (size_t)DD * LL);
    split_launch(wuv, wuvh, wuvl, (size_t)DD * LL);
    split_launch(wo,  woh,  wol,  (size_t)DD * DD);

    // latent = x @ wdkv^T  -> hi/lo planes directly
    hgemm_split_nt<<<dim3(LL / 128, MROWS / 128), 512, GEMM_SMEM_BYTES>>>(
        xh, xl, wdh, wdl, (const float*)0, (float*)0,
        lath, latl, MROWS, LL, DD);

    // k,v = latent @ {wuk,wuv}^T  (fused, fp32 out)
    hgemm_kv<<<dim3(DD / 128, MROWS / 128), 512, KV_SMEM_BYTES>>>(
        lath, latl, wukh, wukl, wuvh, wuvl, kb, vb, MROWS, DD, LL);

    // RoPE
    {
        int total = MROWS * HH * 64;
        rope_kernel<<<(total + 255) / 256, 256>>>(qb, kb);
    }

    // flash attention -> ctx hi/lo planes directly
    flash_tc<<<dim3(SS / 64, HH, BB), 512, FA_SMEM_BYTES>>>(
        qb, kb, vb, ctxh, ctxl);

    // out = ctx @ wo^T + bo
    hgemm_split_nt<<<dim3(DD / 128, MROWS / 128), 512, GEMM_SMEM_BYTES>>>(
        ctxh, ctxl, woh, wol, bo, out,
        (__nv_bfloat16*)0, (__nv_bfloat16*)0, MROWS, DD, DD);
}